// round 8
// baseline (speedup 1.0000x reference)
#include <cuda_runtime.h>
#include <cstdint>

#define BATCH 4
#define SEQ   2048
#define CIN   1024
#define HID   1024

// ---------------- scratch (__device__ globals; alloc APIs forbidden) -------
__device__ float g_qp [BATCH * SEQ * HID];          // 32 MB (tf32-rounded, pre-scaled 2^-5)
__device__ float g_kp [BATCH * SEQ * HID];          // 32 MB (tf32-rounded)
__device__ float g_vp [BATCH * SEQ * HID];          // 32 MB (tf32-rounded)
__device__ float g_S  [(long)BATCH * SEQ * SEQ];    // 64 MB

// ---------------- helpers ---------------------------------------------------
__device__ __forceinline__ uint32_t smem_u32(const void* p) {
    uint32_t r;
    asm("{ .reg .u64 t; cvta.to.shared.u64 t, %1; cvt.u32.u64 %0, t; }"
        : "=r"(r) : "l"(p));
    return r;
}
__device__ __forceinline__ void cpa16(uint32_t dst, const void* src) {
    asm volatile("cp.async.cg.shared.global [%0], [%1], 16;" :: "r"(dst), "l"(src));
}
__device__ __forceinline__ uint32_t f2tf(float x) {
    uint32_t r;
    asm("cvt.rna.tf32.f32 %0, %1;" : "=r"(r) : "f"(x));
    return r;
}
__device__ __forceinline__ float roundtf(float x) { return __uint_as_float(f2tf(x)); }
__device__ __forceinline__ void mma_tf32(float* c, const uint32_t* a, const uint32_t* b) {
    asm volatile("mma.sync.aligned.m16n8k8.row.col.f32.tf32.tf32.f32 "
                 "{%0,%1,%2,%3}, {%4,%5,%6,%7}, {%8,%9}, {%0,%1,%2,%3};"
                 : "+f"(c[0]), "+f"(c[1]), "+f"(c[2]), "+f"(c[3])
                 : "r"(a[0]), "r"(a[1]), "r"(a[2]), "r"(a[3]),
                   "r"(b[0]), "r"(b[1]));
}

// ---------------- tensor-core tf32 GEMM core --------------------------------
// C[M,N] = A[M,K] @ Bop, 128x128 CTA tile, BK=32, 3-stage cp.async pipeline,
// 4 warps (2x2), warp tile 64x64, MMA/LDS lockstep-interleaved double buffer.
//   BNN=false: Bop = B[N,K]^T (B row-major K-contiguous).
//   BNN=true : Bop = B[K,N]   (B row-major N-contiguous).
#define NSTAGE      3
#define STAGE_FLTS  8192          // A 4096 + B 4096 floats (32 KB)
#define GEMM_SMEM   (NSTAGE * STAGE_FLTS * 4)   // 98304 B
#define GTHREADS    128

template<bool CVTA, bool ROUND_OUT, bool BNN>
__device__ __forceinline__
void gemm_body(const float* __restrict__ A, const float* __restrict__ B,
               float* __restrict__ C, int ldA, int ldB, int ldC,
               int KT, int bm, int bn, float alphaOut)
{
    extern __shared__ float sm[];
    const uint32_t sbase = smem_u32(sm);
    const int tid  = threadIdx.x;
    const int lane = tid & 31;
    const int wid  = tid >> 5;        // 0..3
    const int wm = (wid >> 1) * 64;
    const int wn = (wid & 1) * 64;
    const int qr = lane >> 2;         // 0..7
    const int qc = lane & 3;          // 0..3
    const int xm = qr << 2;

    // ---- loader bases (strength-reduced) ----
    const int arow = tid >> 3;            // 0..15
    const int akq  = (tid & 7) * 4;
    const float* Abase = A + (long)(bm * 128 + arow) * ldA + akq;
    const long aStride = (long)16 * ldA;
    const uint32_t adst0 = sbase + (uint32_t)(arow * 32 + (akq ^ ((arow & 7) << 2))) * 4;

    const float* Bbase; long bStride; long bStageStep; uint32_t bdst0;
    if (BNN) {   // tile [k][n], swizzle n^=((k&3)<<3)
        const int bk  = tid >> 5;         // 0..3
        const int bn4 = (tid & 31) * 4;
        Bbase = B + (long)bk * ldB + bn * 128 + bn4;
        bStride = (long)4 * ldB;
        bStageStep = (long)32 * ldB;
        bdst0 = sbase + 16384u + (uint32_t)(bk * 128 + (bn4 ^ ((bk & 3) << 3))) * 4;
    } else {     // tile [n][k], same geometry as A
        Bbase = B + (long)(bn * 128 + arow) * ldB + akq;
        bStride = (long)16 * ldB;
        bStageStep = 32;
        bdst0 = sbase + 16384u + (uint32_t)(arow * 32 + (akq ^ ((arow & 7) << 2))) * 4;
    }

    auto issue_stage = [&](int s) {
        const uint32_t soff = (uint32_t)((s % NSTAGE) * (STAGE_FLTS * 4));
        const float* ap = Abase + s * 32;
        uint32_t ad = adst0 + soff;
#pragma unroll
        for (int t = 0; t < 8; t++) { cpa16(ad, ap); ap += aStride; ad += 2048; }
        const float* bp = Bbase + s * bStageStep;
        uint32_t bd = bdst0 + soff;
#pragma unroll
        for (int t = 0; t < 8; t++) { cpa16(bd, bp); bp += bStride; bd += 2048; }
    };

    // NN fragment column pre-swizzle
    int npr[8];
    if (BNN) {
#pragma unroll
        for (int nt = 0; nt < 8; nt++)
            npr[nt] = (wn + nt * 8 + qr) ^ (qc << 3);
    }

    auto load_frags = [&](const float* As, const float* Bs, int ks,
                          uint32_t af[4][4], uint32_t bf[8][2]) {
        const int k0 = ks * 8;
        const int c0 = (k0 + qc) ^ xm;
        const int c1 = (k0 + 4 + qc) ^ xm;
#pragma unroll
        for (int mt = 0; mt < 4; mt++) {
            int r  = wm + mt * 16 + qr;
            int r8 = r + 8;
            if (CVTA) {
                af[mt][0] = f2tf(As[r  * 32 + c0]);
                af[mt][1] = f2tf(As[r8 * 32 + c0]);
                af[mt][2] = f2tf(As[r  * 32 + c1]);
                af[mt][3] = f2tf(As[r8 * 32 + c1]);
            } else {
                af[mt][0] = __float_as_uint(As[r  * 32 + c0]);
                af[mt][1] = __float_as_uint(As[r8 * 32 + c0]);
                af[mt][2] = __float_as_uint(As[r  * 32 + c1]);
                af[mt][3] = __float_as_uint(As[r8 * 32 + c1]);
            }
        }
#pragma unroll
        for (int nt = 0; nt < 8; nt++) {
            if (BNN) {
                bf[nt][0] = __float_as_uint(Bs[(k0 + qc)     * 128 + npr[nt]]);
                bf[nt][1] = __float_as_uint(Bs[(k0 + 4 + qc) * 128 + npr[nt]]);
            } else {
                int n = wn + nt * 8 + qr;
                bf[nt][0] = __float_as_uint(Bs[n * 32 + c0]);
                bf[nt][1] = __float_as_uint(Bs[n * 32 + c1]);
            }
        }
    };

    float acc[4][8][4];
#pragma unroll
    for (int mt = 0; mt < 4; mt++)
#pragma unroll
        for (int nt = 0; nt < 8; nt++)
#pragma unroll
            for (int i = 0; i < 4; i++) acc[mt][nt][i] = 0.0f;

    // 32 MMAs of the current fragment set, lockstep-interleaved 1:1 with the
    // 32 LDS of the next fragment set (compile-time indices; no branches).
    auto mma_inter = [&](const float* As, const float* Bs,
                         uint32_t afC[4][4], uint32_t bfC[8][2],
                         uint32_t afN[4][4], uint32_t bfN[8][2], int ksn) {
        const int k0 = ksn * 8;
        const int c0 = (k0 + qc) ^ xm;
        const int c1 = (k0 + 4 + qc) ^ xm;
#pragma unroll
        for (int mt = 0; mt < 4; mt++) {
#pragma unroll
            for (int nt = 0; nt < 8; nt++) {
                mma_tf32(acc[mt][nt], afC[mt], bfC[nt]);
                const int j = mt * 8 + nt;
                if (j < 16) {          // A load j: (mt2 = j>>2, i = j&3)
                    const int mt2 = j >> 2, i = j & 3;
                    const int r = wm + mt2 * 16 + qr + (i & 1) * 8;
                    const int cc = (i < 2) ? c0 : c1;
                    const float v = As[r * 32 + cc];
                    afN[mt2][i] = CVTA ? f2tf(v) : __float_as_uint(v);
                } else {               // B load j-16: (nt2, i)
                    const int jj = j - 16, nt2 = jj >> 1, i = jj & 1;
                    if (BNN) {
                        bfN[nt2][i] = __float_as_uint(
                            Bs[(k0 + qc + i * 4) * 128 + npr[nt2]]);
                    } else {
                        const int n = wn + nt2 * 8 + qr;
                        bfN[nt2][i] = __float_as_uint(Bs[n * 32 + (i ? c1 : c0)]);
                    }
                }
            }
        }
    };

    auto run_mma = [&](uint32_t af[4][4], uint32_t bf[8][2]) {
#pragma unroll
        for (int mt = 0; mt < 4; mt++)
#pragma unroll
            for (int nt = 0; nt < 8; nt++)
                mma_tf32(acc[mt][nt], af[mt], bf[nt]);
    };

    // prologue: stages 0 and 1
#pragma unroll
    for (int s = 0; s < 2; s++) {
        issue_stage(s);
        asm volatile("cp.async.commit_group;" ::: "memory");
    }

    for (int kt = 0; kt < KT; kt++) {
        asm volatile("cp.async.wait_group 1;" ::: "memory");
        __syncthreads();

        const float* As = sm + (kt % NSTAGE) * STAGE_FLTS;
        const float* Bs = As + 4096;

        uint32_t afA[4][4], bfA[8][2], afB[4][4], bfB[8][2];
        load_frags(As, Bs, 0, afA, bfA);

        // prefetch stage kt+2: gmem loads overlap the whole MMA body
        int sf = kt + 2;
        if (sf < KT) issue_stage(sf);
        asm volatile("cp.async.commit_group;" ::: "memory");

        mma_inter(As, Bs, afA, bfA, afB, bfB, 1);   // mma ks0, load ks1
        mma_inter(As, Bs, afB, bfB, afA, bfA, 2);   // mma ks1, load ks2
        mma_inter(As, Bs, afA, bfA, afB, bfB, 3);   // mma ks2, load ks3
        run_mma(afB, bfB);                          // mma ks3
    }

#pragma unroll
    for (int mt = 0; mt < 4; mt++) {
        int r = bm * 128 + wm + mt * 16 + qr;
#pragma unroll
        for (int nt = 0; nt < 8; nt++) {
            int col = bn * 128 + wn + nt * 8 + 2 * qc;
            float o0 = acc[mt][nt][0] * alphaOut, o1 = acc[mt][nt][1] * alphaOut;
            float o2 = acc[mt][nt][2] * alphaOut, o3 = acc[mt][nt][3] * alphaOut;
            if (ROUND_OUT) { o0 = roundtf(o0); o1 = roundtf(o1);
                             o2 = roundtf(o2); o3 = roundtf(o3); }
            *(float2*)&C[(long)r * ldC + col]       = make_float2(o0, o1);
            *(float2*)&C[(long)(r + 8) * ldC + col] = make_float2(o2, o3);
        }
    }
}

// Fused projections (NN: W[C][H] read directly):
// z=0 (q,Wq)->qp (pre-scaled 2^-5), z=1 (k,Wk)->kp, z=2 (v,Wq)->vp.
__global__ __launch_bounds__(GTHREADS, 2)
void proj_gemm(const float* __restrict__ qin, const float* __restrict__ kin,
               const float* __restrict__ vin, const float* __restrict__ Wq,
               const float* __restrict__ Wk, float* __restrict__ qp,
               float* __restrict__ kp, float* __restrict__ vp)
{
    const float* A; const float* B; float* C; float alpha = 1.0f;
    if (blockIdx.z == 0)      { A = qin; B = Wq; C = qp; alpha = 1.0f / 32.0f; }
    else if (blockIdx.z == 1) { A = kin; B = Wk; C = kp; }
    else                      { A = vin; B = Wq; C = vp; }
    gemm_body<true, true, true>(A, B, C, CIN, HID, HID, CIN / 32,
                                blockIdx.y, blockIdx.x, alpha);
}

// S = qp @ kp^T (scale folded into qp), triangular grid, heavy blocks first.
__global__ __launch_bounds__(GTHREADS, 2)
void s_gemm(const float* __restrict__ qp, const float* __restrict__ kp,
            float* __restrict__ S)
{
    int idx = 135 - blockIdx.x;           // heavy (high-bm) first
    int acc = 0, bm = 0;
    while (acc + bm + 1 <= idx) { acc += bm + 1; bm++; }
    int bn = idx - acc;
    const long ob = (long)blockIdx.z * SEQ * HID;
    gemm_body<false, false, false>(qp + ob, kp + ob,
                                   S + (long)blockIdx.z * SEQ * SEQ,
                                   HID, HID, SEQ, HID / 32, bm, bn, 1.0f);
}

// out = P @ vp (NN), K causally limited, heavy blocks first.
__global__ __launch_bounds__(GTHREADS, 2)
void pv_gemm(const float* __restrict__ S, const float* __restrict__ vp,
             float* __restrict__ out)
{
    const int bm = (int)(gridDim.y - 1 - blockIdx.y);   // heavy first
    const int bn = blockIdx.x;
    const int KT = (bm + 1) * 4;
    gemm_body<false, false, true>(S + (long)blockIdx.z * SEQ * SEQ,
                                  vp + (long)blockIdx.z * SEQ * HID,
                                  out + (long)blockIdx.z * SEQ * HID,
                                  SEQ, HID, HID, KT, bm, bn, 1.0f);
}

// ---------------- single-pass causal softmax (input pre-scaled) ------------
__global__ __launch_bounds__(256)
void softmax_fast(float* __restrict__ S)
{
    const int t = blockIdx.x, b = blockIdx.y;
    float* row = S + ((long)b * SEQ + t) * SEQ;
    const int n = t + 1;
    const int limit = ((t >> 7) + 1) << 7;
    const int tid = threadIdx.x;
    const int lane = tid & 31, wid = tid >> 5;

    __shared__ float redm[8], reds[8];

    float r[8];
#pragma unroll
    for (int j = 0; j < 8; j++) {
        int i = tid + j * 256;
        r[j] = (i < n) ? row[i] : -1e30f;
    }

    float m = -1e30f;
#pragma unroll
    for (int j = 0; j < 8; j++) m = fmaxf(m, r[j]);
#pragma unroll
    for (int o = 16; o > 0; o >>= 1) m = fmaxf(m, __shfl_xor_sync(~0u, m, o));
    if (lane == 0) redm[wid] = m;
    __syncthreads();
#pragma unroll
    for (int j = 0; j < 8; j++) m = fmaxf(m, redm[j]);

    float sum = 0.0f;
#pragma unroll
    for (int j = 0; j < 8; j++) { r[j] = __expf(r[j] - m); sum += r[j]; }
#pragma unroll
    for (int o = 16; o > 0; o >>= 1) sum += __shfl_xor_sync(~0u, sum, o);
    if (lane == 0) reds[wid] = sum;
    __syncthreads();
    sum = 0.0f;
#pragma unroll
    for (int j = 0; j < 8; j++) sum += reds[j];
    const float inv = 1.0f / sum;

#pragma unroll
    for (int j = 0; j < 8; j++) {
        int i = tid + j * 256;
        if (i < limit) row[i] = (i < n) ? roundtf(r[j] * inv) : 0.0f;
    }
}

// ---------------- launch ---------------------------------------------------
extern "C" void kernel_launch(void* const* d_in, const int* in_sizes, int n_in,
                              void* d_out, int out_size)
{
    const float* kin = (const float*)d_in[1];
    const float* qin = (const float*)d_in[2];
    const float* vin = (const float*)d_in[3];
    const float* Wk  = (const float*)d_in[4];
    const float* Wq  = (const float*)d_in[5];
    float* out = (float*)d_out;

    float *qp, *kp, *vp, *S;
    cudaGetSymbolAddress((void**)&qp, g_qp);
    cudaGetSymbolAddress((void**)&kp, g_kp);
    cudaGetSymbolAddress((void**)&vp, g_vp);
    cudaGetSymbolAddress((void**)&S,  g_S);

    cudaFuncSetAttribute(proj_gemm, cudaFuncAttributeMaxDynamicSharedMemorySize, GEMM_SMEM);
    cudaFuncSetAttribute(s_gemm,    cudaFuncAttributeMaxDynamicSharedMemorySize, GEMM_SMEM);
    cudaFuncSetAttribute(pv_gemm,   cudaFuncAttributeMaxDynamicSharedMemorySize, GEMM_SMEM);

    const int M = BATCH * SEQ;                 // 8192
    dim3 blk(256);
    dim3 gblk(GTHREADS);

    dim3 gProj(HID / 128, M / 128, 3);
    proj_gemm<<<gProj, gblk, GEMM_SMEM>>>(qin, kin, vin, Wq, Wk, qp, kp, vp);

    dim3 gS(136, 1, BATCH);
    s_gemm<<<gS, gblk, GEMM_SMEM>>>(qp, kp, S);

    dim3 gSm(SEQ, BATCH);
    softmax_fast<<<gSm, blk>>>(S);

    dim3 gPV(HID / 128, SEQ / 128, BATCH);
    pv_gemm<<<gPV, gblk, GEMM_SMEM>>>(S, vp, out);
}